// round 15
// baseline (speedup 1.0000x reference)
#include <cuda_runtime.h>
#include <cuda_bf16.h>
#include <math.h>

#define D 256
#define VD 16
#define TM 32          // rows (nodes) per CTA
#define TPAD 36        // padded row length for transposed SMEM tiles (144B, 16B-aligned)
#define CH 128         // edges per shared chunk in edge kernel
#define PF 4           // Qs prefetch depth
#define MAXN 50000
#define MAXE 400000
#define MAXG 256
#define SCB 1024       // scan block size
#define MAXSB ((MAXN + SCB - 1) / SCB)

typedef unsigned long long ull;

// ---- packed f32x2 helpers (sm_103a) ----
__device__ __forceinline__ ull pk2(float lo, float hi) {
    ull r; asm("mov.b64 %0, {%1,%2};" : "=l"(r) : "f"(lo), "f"(hi)); return r;
}
__device__ __forceinline__ ull fma2(ull a, ull b, ull c) {
    ull d; asm("fma.rn.f32x2 %0, %1, %2, %3;" : "=l"(d) : "l"(a), "l"(b), "l"(c)); return d;
}
__device__ __forceinline__ ull add2(ull a, ull b) {
    ull d; asm("add.rn.f32x2 %0, %1, %2;" : "=l"(d) : "l"(a), "l"(b)); return d;
}
__device__ __forceinline__ float2 upk(ull v) {
    float2 f; asm("mov.b64 {%0,%1}, %2;" : "=f"(f.x), "=f"(f.y) : "l"(v)); return f;
}

// ---------------- scratch ----------------
__device__ float g_vn  [MAXN * VD];
__device__ float g_Pd  [MAXN * D];
__device__ float g_Qs  [MAXN * D];
__device__ float g_agg [MAXN * D];
__device__ float g_WeF [17 * D];
__device__ float g_beF [D];
__device__ float g_bP  [D];
__device__ float g_bQ  [D];
__device__ float g_bH  [D];
// pre-duplicated (f32x2-splat) folded weights
__device__ ull   g_AP2 [23 * D];
__device__ ull   g_AQ2 [23 * D];
__device__ ull   g_AH2 [23 * D];
__device__ ull   g_WmF2[D * D];     // 512 KB, L2-resident
__device__ ull   g_WV1 [VD * D];    // dup of Wm1[512:528]
__device__ ull   g_WV2 [VD * D];    // dup of Wn[256:272]
__device__ float g_gsum[MAXG * D];
__device__ float g_gcnt[MAXG];
// CSR sort scratch
__device__ int   g_rowcnt[MAXN];
__device__ int   g_roff  [MAXN + 1];
__device__ int   g_cursor[MAXN];
__device__ int   g_bsum  [MAXSB];
__device__ int   g_boff  [MAXSB];
__device__ int   g_esrc  [MAXE];
__device__ int   g_erow  [MAXE];
__device__ float g_es    [MAXE * 20];

// ---------------- zero small accumulated buffers ----------------
__global__ void k_zero(int N, int G) {
    int i = blockIdx.x * blockDim.x + threadIdx.x;
    int gd = G * D;
    int total = gd + G + N;
    for (; i < total; i += gridDim.x * blockDim.x) {
        if (i < gd)           g_gsum[i] = 0.f;
        else if (i < gd + G)  g_gcnt[i - gd] = 0.f;
        else                  g_rowcnt[i - gd - G] = 0;
    }
}

// ---------------- histogram of dst ----------------
__global__ void k_hist(const int* __restrict__ edge_index, int E) {
    int i = blockIdx.x * blockDim.x + threadIdx.x;
    if (i < E) atomicAdd(&g_rowcnt[edge_index[E + i]], 1);
}

// ---------------- multi-block scan, phase A ----------------
__global__ __launch_bounds__(SCB) void k_scanA(int N) {
    __shared__ int wsum[32];
    int tid = threadIdx.x, lane = tid & 31, wid = tid >> 5;
    int idx = blockIdx.x * SCB + tid;
    int v = (idx < N) ? g_rowcnt[idx] : 0;
    int inc = v;
    #pragma unroll
    for (int o = 1; o < 32; o <<= 1) {
        int t = __shfl_up_sync(0xFFFFFFFFu, inc, o);
        if (lane >= o) inc += t;
    }
    if (lane == 31) wsum[wid] = inc;
    __syncthreads();
    if (wid == 0) {
        int s = wsum[lane];
        #pragma unroll
        for (int o = 1; o < 32; o <<= 1) {
            int t = __shfl_up_sync(0xFFFFFFFFu, s, o);
            if (lane >= o) s += t;
        }
        wsum[lane] = s;
    }
    __syncthreads();
    int excl = (wid ? wsum[wid - 1] : 0) + inc - v;
    if (idx < N) g_roff[idx] = excl;
    if (tid == SCB - 1) g_bsum[blockIdx.x] = excl + v;
}

// ---------------- phase B ----------------
__global__ __launch_bounds__(64) void k_scanB(int nb, int N) {
    __shared__ int sh[MAXSB];
    int tid = threadIdx.x;
    for (int i = tid; i < nb; i += 64) sh[i] = g_bsum[i];
    __syncthreads();
    if (tid == 0) {
        int run = 0;
        for (int i = 0; i < nb; i++) { int t = sh[i]; sh[i] = run; run += t; }
        g_roff[N] = run;
    }
    __syncthreads();
    for (int i = tid; i < nb; i += 64) g_boff[i] = sh[i];
}

// ---------------- phase C ----------------
__global__ __launch_bounds__(SCB) void k_scanC(int N) {
    int idx = blockIdx.x * SCB + threadIdx.x;
    if (idx < N) {
        int v = g_roff[idx] + g_boff[blockIdx.x];
        g_roff[idx] = v;
        g_cursor[idx] = v;
    }
}

// ---------------- scatter edges into sorted (by dst) arrays ----------------
__global__ void k_scatter(const int* __restrict__ edge_index,
                          const float* __restrict__ edge_s, int E) {
    int e = blockIdx.x * blockDim.x + threadIdx.x;
    if (e >= E) return;
    int src = edge_index[e];
    int dst = edge_index[E + e];
    int pos = atomicAdd(&g_cursor[dst], 1);
    g_esrc[pos] = src;
    g_erow[pos] = dst;
    const float* es = edge_s + (long long)e * 17;
    float v[17];
    #pragma unroll
    for (int k = 0; k < 17; k++) v[k] = es[k];
    float4* dst4 = (float4*)&g_es[(long long)pos * 20];
    dst4[0] = make_float4(v[0], v[1], v[2], v[3]);
    dst4[1] = make_float4(v[4], v[5], v[6], v[7]);
    dst4[2] = make_float4(v[8], v[9], v[10], v[11]);
    dst4[3] = make_float4(v[12], v[13], v[14], v[15]);
    g_es[(long long)pos * 20 + 16] = v[16];
}

// ---------------- merged folds ----------------
// blocks: [0,18) wef | [18,42) fold2 | [42,322) fold3 | [322,338) W1V dup | [338,354) WnV dup
__global__ __launch_bounds__(D) void k_folds(const float* __restrict__ We,
                                             const float* __restrict__ be,
                                             const float* __restrict__ Wm1,
                                             const float* __restrict__ Ws,
                                             const float* __restrict__ bs,
                                             const float* __restrict__ bm1,
                                             const float* __restrict__ Wm2,
                                             const float* __restrict__ bm2,
                                             const float* __restrict__ Wn,
                                             const float* __restrict__ bn) {
    __shared__ float row[D];
    int j = threadIdx.x, bb = blockIdx.x;
    if (bb < 18) {
        int b = bb;
        row[j] = (b < 17) ? We[b * D + j] : be[j];
        __syncthreads();
        float a0 = 0.f, a1 = 0.f, a2 = 0.f, a3 = 0.f;
        #pragma unroll 8
        for (int c = 0; c < D; c += 4) {
            a0 += row[c + 0] * Wm1[(528 + c + 0) * D + j];
            a1 += row[c + 1] * Wm1[(528 + c + 1) * D + j];
            a2 += row[c + 2] * Wm1[(528 + c + 2) * D + j];
            a3 += row[c + 3] * Wm1[(528 + c + 3) * D + j];
        }
        float a = (a0 + a1) + (a2 + a3);
        if (b < 17) g_WeF[b * D + j] = a;
        else        g_beF[j] = a;
    } else if (bb < 42) {
        int b = bb - 18;
        row[j] = (b < 23) ? Ws[b * D + j] : bs[j];
        __syncthreads();
        float p0 = 0.f, p1 = 0.f, q0 = 0.f, q1 = 0.f;
        #pragma unroll 8
        for (int c = 0; c < D; c += 2) {
            float r0 = row[c], r1 = row[c + 1];
            p0 += r0 * Wm1[(c + 0) * D + j];
            p1 += r1 * Wm1[(c + 1) * D + j];
            q0 += r0 * Wm1[(D + c + 0) * D + j];
            q1 += r1 * Wm1[(D + c + 1) * D + j];
        }
        float aP = p0 + p1, aQ = q0 + q1;
        if (b < 23) { g_AP2[b * D + j] = pk2(aP, aP); g_AQ2[b * D + j] = pk2(aQ, aQ); }
        else        { g_bP[j] = aP + bm1[j]; g_bQ[j] = aQ; }
    } else if (bb < 322) {
        int b = bb - 42;
        if (b < D)            row[j] = Wm2[b * D + j];
        else if (b < D + 23)  row[j] = Ws[(b - D) * D + j];
        else                  row[j] = bs[j] + bm2[j];
        __syncthreads();
        float a0 = 0.f, a1 = 0.f, a2 = 0.f, a3 = 0.f;
        #pragma unroll 8
        for (int c = 0; c < D; c += 4) {
            a0 += row[c + 0] * Wn[(c + 0) * D + j];
            a1 += row[c + 1] * Wn[(c + 1) * D + j];
            a2 += row[c + 2] * Wn[(c + 2) * D + j];
            a3 += row[c + 3] * Wn[(c + 3) * D + j];
        }
        float a = (a0 + a1) + (a2 + a3);
        if (b < D)            g_WmF2[b * D + j] = pk2(a, a);
        else if (b < D + 23)  g_AH2[(b - D) * D + j] = pk2(a, a);
        else                  g_bH[j] = a + bn[j];
    } else if (bb < 338) {
        int k = bb - 322;
        float w = Wm1[(512 + k) * D + j];
        g_WV1[k * D + j] = pk2(w, w);
    } else {
        int k = bb - 338;
        float w = Wn[(D + k) * D + j];
        g_WV2[k * D + j] = pk2(w, w);
    }
}

// ---------------- node embed + first-layer precompute (4col x 8row tiled) ----------------
__global__ __launch_bounds__(D) void k_nodeEmb(const float* __restrict__ node_s,
                                               const float* __restrict__ node_v,
                                               const float* __restrict__ Wv,
                                               const float* __restrict__ bv,
                                               int N) {
    __shared__ __align__(16) float nsT[23][TM];
    __shared__ float nv[TM][12];
    __shared__ __align__(16) float vnT[VD][TM + 4];
    __shared__ float sWv[4 * VD];
    __shared__ float sbv[VD];
    int j = threadIdx.x;
    int n0 = blockIdx.x * TM;
    int nvld = min(TM, N - n0);
    int c0 = (j & 63) * 4;
    int r0 = (j >> 6) * 8;

    for (int i = j; i < TM * 23; i += D) {
        int r = i / 23, k = i % 23;
        nsT[k][r] = (r < nvld) ? node_s[(n0 + r) * 23 + k] : 0.f;
    }
    for (int i = j; i < nvld * 12; i += D) nv[i / 12][i % 12] = node_v[n0 * 12 + i];
    if (j < 4 * VD) sWv[j] = Wv[j];
    if (j < VD) sbv[j] = bv[j];
    __syncthreads();

    for (int idx = j; idx < TM * VD; idx += D) {
        int r = idx / VD, o = idx % VD;
        float val = 0.f;
        if (r < nvld) {
            float x = sbv[o], y = sbv[o], z = sbv[o];
            #pragma unroll
            for (int k = 0; k < 4; k++) {
                float w = sWv[k * VD + o];
                x += nv[r][k * 3 + 0] * w;
                y += nv[r][k * 3 + 1] * w;
                z += nv[r][k * 3 + 2] * w;
            }
            val = sqrtf(x * x + y * y + z * z);
            g_vn[(n0 + r) * VD + o] = val;
        }
        vnT[o][r] = val;
    }
    __syncthreads();

    // acc[cc][pp]: col c0+cc, row pair (r0+2pp, r0+2pp+1)
    ull accP[4][4], accQ[4][4];
    {
        float4 bp = *(const float4*)&g_bP[c0];
        float4 bq = *(const float4*)&g_bQ[c0];
        #pragma unroll
        for (int pp = 0; pp < 4; pp++) {
            accP[0][pp] = pk2(bp.x, bp.x); accQ[0][pp] = pk2(bq.x, bq.x);
            accP[1][pp] = pk2(bp.y, bp.y); accQ[1][pp] = pk2(bq.y, bq.y);
            accP[2][pp] = pk2(bp.z, bp.z); accQ[2][pp] = pk2(bq.z, bq.z);
            accP[3][pp] = pk2(bp.w, bp.w); accQ[3][pp] = pk2(bq.w, bq.w);
        }
    }

    #pragma unroll 2
    for (int k = 0; k < 23; k++) {
        const ulonglong2* wp = (const ulonglong2*)&g_AP2[k * D + c0];
        const ulonglong2* wq = (const ulonglong2*)&g_AQ2[k * D + c0];
        ulonglong2 pa = __ldg(wp), pb = __ldg(wp + 1);
        ulonglong2 qa = __ldg(wq), qb = __ldg(wq + 1);
        const ull* rp = (const ull*)&nsT[k][r0];
        #pragma unroll
        for (int pp = 0; pp < 4; pp++) {
            ull a = rp[pp];
            accP[0][pp] = fma2(a, pa.x, accP[0][pp]);
            accP[1][pp] = fma2(a, pa.y, accP[1][pp]);
            accP[2][pp] = fma2(a, pb.x, accP[2][pp]);
            accP[3][pp] = fma2(a, pb.y, accP[3][pp]);
            accQ[0][pp] = fma2(a, qa.x, accQ[0][pp]);
            accQ[1][pp] = fma2(a, qa.y, accQ[1][pp]);
            accQ[2][pp] = fma2(a, qb.x, accQ[2][pp]);
            accQ[3][pp] = fma2(a, qb.y, accQ[3][pp]);
        }
    }
    #pragma unroll 2
    for (int k = 0; k < VD; k++) {
        const ulonglong2* wv = (const ulonglong2*)&g_WV1[k * D + c0];
        ulonglong2 va = __ldg(wv), vb = __ldg(wv + 1);
        const ull* rp = (const ull*)&vnT[k][r0];
        #pragma unroll
        for (int pp = 0; pp < 4; pp++) {
            ull a = rp[pp];
            accQ[0][pp] = fma2(a, va.x, accQ[0][pp]);
            accQ[1][pp] = fma2(a, va.y, accQ[1][pp]);
            accQ[2][pp] = fma2(a, vb.x, accQ[2][pp]);
            accQ[3][pp] = fma2(a, vb.y, accQ[3][pp]);
        }
    }
    #pragma unroll
    for (int pp = 0; pp < 4; pp++) {
        float2 p0 = upk(accP[0][pp]), p1 = upk(accP[1][pp]);
        float2 p2 = upk(accP[2][pp]), p3 = upk(accP[3][pp]);
        float2 q0 = upk(accQ[0][pp]), q1 = upk(accQ[1][pp]);
        float2 q2 = upk(accQ[2][pp]), q3 = upk(accQ[3][pp]);
        int ra = r0 + 2 * pp, rb = ra + 1;
        if (ra < nvld) {
            *(float4*)&g_Pd[(n0 + ra) * D + c0] = make_float4(p0.x, p1.x, p2.x, p3.x);
            *(float4*)&g_Qs[(n0 + ra) * D + c0] = make_float4(q0.x, q1.x, q2.x, q3.x);
        }
        if (rb < nvld) {
            *(float4*)&g_Pd[(n0 + rb) * D + c0] = make_float4(p0.y, p1.y, p2.y, p3.y);
            *(float4*)&g_Qs[(n0 + rb) * D + c0] = make_float4(q0.y, q1.y, q2.y, q3.y);
        }
    }
}

// ---------------- edge kernel (CSR, f32x2 dot, PF-deep Qs prefetch) ----------------
__global__ __launch_bounds__(D) void k_edgeCSR(int N) {
    __shared__ float sPd[TM * D];
    __shared__ __align__(16) float sEs[CH][20];
    __shared__ int   sSrc[CH];
    __shared__ int   sRow[CH];
    int j = threadIdx.x;
    int n0 = blockIdx.x * TM;
    int nvld = min(TM, N - n0);

    for (int i = j; i < nvld * D; i += D) {
        int r = i >> 8, k = i & 255;
        sPd[r * D + k] = g_Pd[(n0 + r) * D + k];
    }
    int e0 = g_roff[n0];
    int e1 = g_roff[n0 + nvld];

    ull w2[8];
    float wf16;
    {
        float wf[17];
        #pragma unroll
        for (int k = 0; k < 17; k++) wf[k] = g_WeF[k * D + j];
        #pragma unroll
        for (int k = 0; k < 8; k++) w2[k] = pk2(wf[2 * k], wf[2 * k + 1]);
        wf16 = wf[16];
    }
    float bef = g_beF[j];

    int cur = -1;
    float a = 0.f, bpd = 0.f;

    for (int base = e0; base < e1; base += CH) {
        int cnt = min(CH, e1 - base);
        __syncthreads();
        for (int t = j; t < cnt * 20; t += D)
            sEs[t / 20][t % 20] = g_es[(long long)base * 20 + t];
        for (int t = j; t < cnt; t += D) {
            sSrc[t] = g_esrc[base + t];
            sRow[t] = g_erow[base + t] - n0;
        }
        __syncthreads();

        float q[PF];
        #pragma unroll
        for (int p = 0; p < PF; p++)
            q[p] = (p < cnt) ? __ldg(&g_Qs[sSrc[p] * D + j]) : 0.f;

        for (int i = 0; i < cnt; i += PF) {
            #pragma unroll
            for (int u = 0; u < PF; u++) {
                int idx = i + u;
                if (idx >= cnt) break;
                float qc = q[u];
                int nidx = idx + PF;
                q[u] = (nidx < cnt) ? __ldg(&g_Qs[sSrc[nidx] * D + j]) : 0.f;
                int r = sRow[idx];
                if (r != cur) {
                    if (cur >= 0) g_agg[(n0 + cur) * D + j] = a;
                    cur = r; a = 0.f;
                    bpd = bef + sPd[r * D + j];
                }
                const ulonglong2* ep = (const ulonglong2*)sEs[idx];
                ulonglong2 p0 = ep[0], p1 = ep[1];
                ull ha = pk2(bpd + qc, sEs[idx][16] * wf16);
                ull hb = pk2(0.f, 0.f);
                ha = fma2(p0.x, w2[0], ha);
                hb = fma2(p0.y, w2[1], hb);
                ha = fma2(p1.x, w2[2], ha);
                hb = fma2(p1.y, w2[3], hb);
                ulonglong2 p2 = ep[2], p3 = ep[3];
                ha = fma2(p2.x, w2[4], ha);
                hb = fma2(p2.y, w2[5], hb);
                ha = fma2(p3.x, w2[6], ha);
                hb = fma2(p3.y, w2[7], hb);
                float2 hf = upk(add2(ha, hb));
                a += fmaxf(hf.x + hf.y, 0.f);
            }
        }
    }
    if (cur >= 0) g_agg[(n0 + cur) * D + j] = a;
}

// ---------------- node output: 4col x 8row register-tiled GEMM + LN + pooling ----------------
__global__ __launch_bounds__(D) void k_node2(const float* __restrict__ node_s,
                                             const float* __restrict__ gamma,
                                             const float* __restrict__ beta,
                                             const int* __restrict__ batch,
                                             int N) {
    __shared__ __align__(16) float aT[D * TPAD];
    __shared__ __align__(16) float ns2T[23][TM];
    __shared__ __align__(16) float vnT[VD][TPAD];
    __shared__ float rc[TM];
    __shared__ float red[2][TM];
    __shared__ int sb[TM];
    int j = threadIdx.x;
    int n0 = blockIdx.x * TM;
    int nvld = min(TM, N - n0);

    int c0 = (j & 63) * 4;
    int r0 = (j >> 6) * 8;

    if (j < TM) {
        float deg = 0.f;
        if (j < nvld) {
            int n = n0 + j;
            deg = (float)(g_roff[n + 1] - g_roff[n]);
            sb[j] = batch[n];
        } else sb[j] = 0;
        rc[j] = 1.f / fmaxf(deg, 1.f);
    }
    for (int i = j; i < TM * 23; i += D) {
        int r = i / 23, k = i % 23;
        ns2T[k][r] = (r < nvld) ? node_s[(n0 + r) * 23 + k] : 0.f;
    }
    for (int i = j; i < TM * VD; i += D) {
        int r = i / VD, k = i % VD;
        vnT[k][r] = (r < nvld) ? g_vn[(n0 + r) * VD + k] : 0.f;
    }
    __syncthreads();
    for (int i = j; i < TM * D; i += D) {
        int r = i >> 8, k = i & 255;
        aT[k * TPAD + r] = (r < nvld) ? g_agg[(n0 + r) * D + k] * rc[r] : 0.f;
    }
    __syncthreads();

    ull acc2[4][4];
    {
        float4 b4 = *(const float4*)&g_bH[c0];
        #pragma unroll
        for (int pp = 0; pp < 4; pp++) {
            acc2[0][pp] = pk2(b4.x, b4.x);
            acc2[1][pp] = pk2(b4.y, b4.y);
            acc2[2][pp] = pk2(b4.z, b4.z);
            acc2[3][pp] = pk2(b4.w, b4.w);
        }
    }

    #pragma unroll 2
    for (int k = 0; k < 23; k++) {
        const ulonglong2* wp = (const ulonglong2*)&g_AH2[k * D + c0];
        ulonglong2 wa = __ldg(wp), wb = __ldg(wp + 1);
        const ull* rp = (const ull*)&ns2T[k][r0];
        #pragma unroll
        for (int pp = 0; pp < 4; pp++) {
            ull a = rp[pp];
            acc2[0][pp] = fma2(a, wa.x, acc2[0][pp]);
            acc2[1][pp] = fma2(a, wa.y, acc2[1][pp]);
            acc2[2][pp] = fma2(a, wb.x, acc2[2][pp]);
            acc2[3][pp] = fma2(a, wb.y, acc2[3][pp]);
        }
    }
    #pragma unroll 2
    for (int k = 0; k < VD; k++) {
        const ulonglong2* wv = (const ulonglong2*)&g_WV2[k * D + c0];
        ulonglong2 wa = __ldg(wv), wb = __ldg(wv + 1);
        const ull* rp = (const ull*)&vnT[k][r0];
        #pragma unroll
        for (int pp = 0; pp < 4; pp++) {
            ull a = rp[pp];
            acc2[0][pp] = fma2(a, wa.x, acc2[0][pp]);
            acc2[1][pp] = fma2(a, wa.y, acc2[1][pp]);
            acc2[2][pp] = fma2(a, wb.x, acc2[2][pp]);
            acc2[3][pp] = fma2(a, wb.y, acc2[3][pp]);
        }
    }
    // main 256-K GEMM over pre-duplicated g_WmF2, prefetched
    {
        const ulonglong2* wp = (const ulonglong2*)&g_WmF2[c0];
        ulonglong2 wa = __ldg(wp), wb = __ldg(wp + 1);
        #pragma unroll 4
        for (int k = 0; k < D; k++) {
            ulonglong2 ca = wa, cb = wb;
            if (k + 1 < D) {
                const ulonglong2* wn = (const ulonglong2*)&g_WmF2[(k + 1) * D + c0];
                wa = __ldg(wn); wb = __ldg(wn + 1);
            }
            const ull* rp = (const ull*)&aT[k * TPAD + r0];
            ull a0 = rp[0], a1 = rp[1], a2 = rp[2], a3 = rp[3];
            acc2[0][0] = fma2(a0, ca.x, acc2[0][0]);
            acc2[1][0] = fma2(a0, ca.y, acc2[1][0]);
            acc2[2][0] = fma2(a0, cb.x, acc2[2][0]);
            acc2[3][0] = fma2(a0, cb.y, acc2[3][0]);
            acc2[0][1] = fma2(a1, ca.x, acc2[0][1]);
            acc2[1][1] = fma2(a1, ca.y, acc2[1][1]);
            acc2[2][1] = fma2(a1, cb.x, acc2[2][1]);
            acc2[3][1] = fma2(a1, cb.y, acc2[3][1]);
            acc2[0][2] = fma2(a2, ca.x, acc2[0][2]);
            acc2[1][2] = fma2(a2, ca.y, acc2[1][2]);
            acc2[2][2] = fma2(a2, cb.x, acc2[2][2]);
            acc2[3][2] = fma2(a2, cb.y, acc2[3][2]);
            acc2[0][3] = fma2(a3, ca.x, acc2[0][3]);
            acc2[1][3] = fma2(a3, ca.y, acc2[1][3]);
            acc2[2][3] = fma2(a3, cb.x, acc2[2][3]);
            acc2[3][3] = fma2(a3, cb.y, acc2[3][3]);
        }
    }
    __syncthreads();                 // done reading aT; reuse as h [TM][D]
    float* hS = aT;
    #pragma unroll
    for (int pp = 0; pp < 4; pp++) {
        float2 f0 = upk(acc2[0][pp]), f1 = upk(acc2[1][pp]);
        float2 f2 = upk(acc2[2][pp]), f3 = upk(acc2[3][pp]);
        *(float4*)&hS[(r0 + 2 * pp) * D + c0]     = make_float4(f0.x, f1.x, f2.x, f3.x);
        *(float4*)&hS[(r0 + 2 * pp + 1) * D + c0] = make_float4(f0.y, f1.y, f2.y, f3.y);
    }
    __syncthreads();

    int wid = j >> 5, lane = j & 31;
    for (int r = wid; r < TM; r += 8) {
        float s1 = 0.f, s2 = 0.f;
        #pragma unroll
        for (int c = lane; c < D; c += 32) { float x = hS[r * D + c]; s1 += x; s2 += x * x; }
        #pragma unroll
        for (int o = 16; o; o >>= 1) {
            s1 += __shfl_xor_sync(0xFFFFFFFFu, s1, o);
            s2 += __shfl_xor_sync(0xFFFFFFFFu, s2, o);
        }
        if (lane == 0) {
            float mu = s1 * (1.f / D);
            float var = s2 * (1.f / D) - mu * mu;
            red[0][r] = mu;
            red[1][r] = rsqrtf(var + 1e-5f);
        }
    }
    __syncthreads();

    float4 ga = *(const float4*)&gamma[c0];
    float4 be = *(const float4*)&beta[c0];
    #pragma unroll
    for (int pp = 0; pp < 4; pp++) {
        float2 f0 = upk(acc2[0][pp]), f1 = upk(acc2[1][pp]);
        float2 f2 = upk(acc2[2][pp]), f3 = upk(acc2[3][pp]);
        int ra = r0 + 2 * pp, rb = ra + 1;
        if (ra < nvld) {
            float mu = red[0][ra], rs = red[1][ra];
            float* gs = &g_gsum[sb[ra] * D + c0];
            atomicAdd(gs + 0, fmaxf((f0.x - mu) * rs * ga.x + be.x, 0.f));
            atomicAdd(gs + 1, fmaxf((f1.x - mu) * rs * ga.y + be.y, 0.f));
            atomicAdd(gs + 2, fmaxf((f2.x - mu) * rs * ga.z + be.z, 0.f));
            atomicAdd(gs + 3, fmaxf((f3.x - mu) * rs * ga.w + be.w, 0.f));
        }
        if (rb < nvld) {
            float mu = red[0][rb], rs = red[1][rb];
            float* gs = &g_gsum[sb[rb] * D + c0];
            atomicAdd(gs + 0, fmaxf((f0.y - mu) * rs * ga.x + be.x, 0.f));
            atomicAdd(gs + 1, fmaxf((f1.y - mu) * rs * ga.y + be.y, 0.f));
            atomicAdd(gs + 2, fmaxf((f2.y - mu) * rs * ga.z + be.z, 0.f));
            atomicAdd(gs + 3, fmaxf((f3.y - mu) * rs * ga.w + be.w, 0.f));
        }
    }
    if (j < nvld) atomicAdd(&g_gcnt[sb[j]], 1.f);
}

// ---------------- final: divide pooled sums ----------------
__global__ __launch_bounds__(D) void k_final(float* __restrict__ out, int G) {
    int g = blockIdx.x, j = threadIdx.x;
    out[g * D + j] = g_gsum[g * D + j] / fmaxf(g_gcnt[g], 1.f);
}

// ---------------- launch ----------------
extern "C" void kernel_launch(void* const* d_in, const int* in_sizes, int n_in,
                              void* d_out, int out_size) {
    const float* node_s = (const float*)d_in[0];
    const float* node_v = (const float*)d_in[1];
    const float* edge_s = (const float*)d_in[2];
    const int*   edge_index = (const int*)d_in[3];
    const int*   batch  = (const int*)d_in[4];
    const float* Ws  = (const float*)d_in[5];
    const float* bs  = (const float*)d_in[6];
    const float* Wv  = (const float*)d_in[7];
    const float* bv  = (const float*)d_in[8];
    const float* We  = (const float*)d_in[9];
    const float* be  = (const float*)d_in[10];
    const float* Wm1 = (const float*)d_in[11];
    const float* bm1 = (const float*)d_in[12];
    const float* Wm2 = (const float*)d_in[13];
    const float* bm2 = (const float*)d_in[14];
    const float* Wn  = (const float*)d_in[15];
    const float* bn  = (const float*)d_in[16];
    const float* gamma = (const float*)d_in[17];
    const float* beta  = (const float*)d_in[18];

    int N = in_sizes[0] / 23;
    int E = in_sizes[2] / 17;
    int G = out_size / D;
    int nb = (N + SCB - 1) / SCB;

    k_zero<<<256, 256>>>(N, G);
    k_hist<<<(E + 255) / 256, 256>>>(edge_index, E);
    k_folds<<<354, D>>>(We, be, Wm1, Ws, bs, bm1, Wm2, bm2, Wn, bn);
    k_scanA<<<nb, SCB>>>(N);
    k_scanB<<<1, 64>>>(nb, N);
    k_scanC<<<nb, SCB>>>(N);
    k_scatter<<<(E + 255) / 256, 256>>>(edge_index, edge_s, E);
    k_nodeEmb<<<(N + TM - 1) / TM, D>>>(node_s, node_v, Wv, bv, N);
    k_edgeCSR<<<(N + TM - 1) / TM, D>>>(N);
    k_node2<<<(N + TM - 1) / TM, D>>>(node_s, gamma, beta, batch, N);
    k_final<<<G, D>>>((float*)d_out, G);
}